// round 16
// baseline (speedup 1.0000x reference)
#include <cuda_runtime.h>
#include <cuda_bf16.h>
#include <cuda_fp16.h>
#include <math.h>

#define HID 128
#define MAXN 50000
#define MAXE 600000

// ---------------- scratch (static device memory; no allocs allowed) ----------------
static const size_t NHs   = (size_t)MAXN * HID;
static const size_t O_HS0  = 0;                       // __half[NHs]
static const size_t O_HS1  = O_HS0 + NHs / 2;         // __half[NHs]
static const size_t O_XPH  = O_HS1 + NHs / 2;         // __half[NHs]
static const size_t O_XAH  = O_XPH + NHs / 2;         // __half[NHs]
static const size_t O_NB   = O_XAH + NHs / 2;         // 4 x __half[NHs]
static const size_t O_AS0  = O_NB + 4 * (NHs / 2);
static const size_t O_AS1  = O_AS0 + MAXN + 64;
static const size_t O_V    = O_AS1 + MAXN + 64;       // 4 x 128 floats
static const size_t O_POOL = O_V + 4 * 128;
static const size_t O_WT   = O_POOL + 2 * 64 * HID;   // __half[4*128*128] transposed Wsrc
static const size_t SCRATCH_FLOATS = O_WT + 4 * HID * HID / 2;

__device__ float g_scratch[SCRATCH_FLOATS];
__device__ int   g_rowptr[2][MAXN + 1];
__device__ int   g_csrc[2][MAXE];
__device__ int   g_cursor[2][MAXN];
__device__ int   g_aggs[2][64];      // lookback aggregates (sentinel -1)

// ---------------- prep: f32->f16 convert inputs + zero cursors/pool + aggs + Wt ------
__global__ void prep_kernel(const float* __restrict__ Xp, const float* __restrict__ Xa,
                            __half* __restrict__ XhBase,
                            int* __restrict__ cursor, float* __restrict__ pool,
                            int* __restrict__ aggs,
                            const float* __restrict__ Wsrc, __half* __restrict__ Wth,
                            int per4, int cvtb, int zerob, int n2, int np)
{
    int bx = blockIdx.x;
    if (bx < cvtb) {
        int i = bx * 256 + threadIdx.x;
        if (i >= 2 * per4) return;
        const float* X = (i < per4) ? Xp : Xa;
        int j = (i < per4) ? i : i - per4;
        float4 v = __ldg((const float4*)X + j);
        __half2 h01 = __floats2half2_rn(v.x, v.y);
        __half2 h23 = __floats2half2_rn(v.z, v.w);
        ((uint2*)XhBase)[i] = make_uint2(*(unsigned int*)&h01, *(unsigned int*)&h23);
    } else if (bx < cvtb + zerob) {
        int i = (bx - cvtb) * 256 + threadIdx.x;
        if (i < n2) cursor[i] = 0;
        if (i < np) pool[i] = 0.f;
        if (i < 128) aggs[i] = -1;
    } else {
        int i = (bx - cvtb - zerob) * 256 + threadIdx.x;   // 0 .. 4*16384-1
        if (i >= 4 * HID * HID) return;
        int pi = i >> 14;
        int rem = i & 16383;
        int k = rem >> 7, nn = rem & 127;
        Wth[(size_t)pi * HID * HID + nn * HID + k] =
            __float2half(__ldg(Wsrc + (size_t)pi * HID * HID + k * HID + nn));
    }
}

// ---------------- hist (vectorized int4, both edge types) + wv vectors ---------------
__global__ void hist_wv_kernel(const int* __restrict__ e0, const int* __restrict__ e1,
                               int* __restrict__ cnt, int ne,
                               const float* __restrict__ Wdst,
                               const float* __restrict__ att_dst, float* __restrict__ vbuf)
{
    int et = blockIdx.y;
    int histb = gridDim.x - 32;
    if ((int)blockIdx.x < histb) {
        const int* dst = (et ? e1 : e0) + ne;
        int i4 = blockIdx.x * blockDim.x + threadIdx.x;
        int ne4 = ne >> 2;
        int* c = cnt + (size_t)et * MAXN;
        if (i4 < ne4) {
            int4 d = __ldg((const int4*)dst + i4);
            atomicAdd(c + d.x, 1);
            atomicAdd(c + d.y, 1);
            atomicAdd(c + d.z, 1);
            atomicAdd(c + d.w, 1);
        }
        int tail0 = ne4 << 2;
        int t = tail0 + i4;
        if (i4 < (ne - tail0)) atomicAdd(c + __ldg(dst + t), 1);
    } else {
        int dx = blockIdx.x - histb;
        int gw = (et * 32 + dx) * 8 + (threadIdx.x >> 5);
        int lane = threadIdx.x & 31;
        int pi = gw >> 7, k = gw & 127;
        float4 wv = __ldg((const float4*)(Wdst + (size_t)pi * HID * HID + (size_t)k * HID) + lane);
        float4 av = __ldg((const float4*)(att_dst + (size_t)pi * HID) + lane);
        float s = wv.x*av.x + wv.y*av.y + wv.z*av.z + wv.w*av.w;
        #pragma unroll
        for (int o = 16; o; o >>= 1) s += __shfl_xor_sync(0xFFFFFFFFu, s, o);
        if (lane == 0) vbuf[gw] = s;
    }
}

// ---------------- HMMA GEMM with ldmatrix fragment loads -----------------------------
#define XS_STR 136
__global__ void __launch_bounds__(256) gemm_mma2_kernel(
    const __half* __restrict__ Xp, const __half* __restrict__ Xa,
    const __half* __restrict__ Wth, const float* __restrict__ att_src, int l,
    __half* __restrict__ Hs0, __half* __restrict__ Hs1,
    float* __restrict__ As0, float* __restrict__ As1, int n)
{
    const int et = blockIdx.y;
    const __half* X = et ? Xa : Xp;
    const int pi = l * 2 + et;
    const __half* Wt_g = Wth + (size_t)pi * HID * HID;
    const float* att = att_src + (size_t)pi * HID;
    __half* Hout = et ? Hs1 : Hs0;
    float*  aout = et ? As1 : As0;

    extern __shared__ __half sm[];
    __half* Xs = sm;
    __half* Wt = sm + 128 * XS_STR;

    const int tid  = threadIdx.x;
    const int row0 = blockIdx.x * 128;

    for (int i = tid; i < 128 * 16; i += 256) {
        int r = i >> 4, c8 = (i & 15) * 8;
        uint4 wv = __ldg((const uint4*)(Wt_g + r * HID + c8));
        *(uint4*)(Wt + r * XS_STR + c8) = wv;
        int gr = row0 + r;
        uint4 v = make_uint4(0u, 0u, 0u, 0u);
        if (gr < n) v = __ldg((const uint4*)(X + (size_t)gr * HID + c8));
        *(uint4*)(Xs + r * XS_STR + c8) = v;
    }
    __syncthreads();

    const int w    = tid >> 5;
    const int lane = tid & 31;
    const int r    = lane >> 2;
    const int q    = lane & 3;

    float acc[16][4];
    #pragma unroll
    for (int t = 0; t < 16; t++)
        #pragma unroll
        for (int j = 0; j < 4; j++) acc[t][j] = 0.f;

    // ldmatrix lane addressing:
    // A x4: lanes 0-15 -> rows (w*16 + lane&15) at k0;   lanes 16-31 -> same rows at k0+8
    // B x4: lanes 0-7 -> n=t8..t8+7 @k0; 8-15 -> n=t8+8..15 @k0; 16-23/24-31 same @k0+8
    unsigned int xs_addr = (unsigned int)__cvta_generic_to_shared(
        Xs + (w * 16 + (lane & 15)) * XS_STR + ((lane >> 4) << 3));
    unsigned int wt_addr = (unsigned int)__cvta_generic_to_shared(
        Wt + ((lane & 7) + ((lane >> 3) & 1) * 8) * XS_STR + ((lane >> 4) << 3));

    #pragma unroll
    for (int k0 = 0; k0 < HID; k0 += 16) {
        unsigned int a0, a1, a2, a3;
        asm volatile("ldmatrix.sync.aligned.m8n8.x4.shared.b16 {%0,%1,%2,%3}, [%4];"
                     : "=r"(a0), "=r"(a1), "=r"(a2), "=r"(a3)
                     : "r"(xs_addr + k0 * 2));
        #pragma unroll
        for (int t = 0; t < 16; t += 2) {
            unsigned int b0, b1, b2, b3;
            asm volatile("ldmatrix.sync.aligned.m8n8.x4.shared.b16 {%0,%1,%2,%3}, [%4];"
                         : "=r"(b0), "=r"(b1), "=r"(b2), "=r"(b3)
                         : "r"(wt_addr + (unsigned int)((t * 8 * XS_STR + k0) * 2)));
            asm volatile(
                "mma.sync.aligned.m16n8k16.row.col.f32.f16.f16.f32 "
                "{%0,%1,%2,%3}, {%4,%5,%6,%7}, {%8,%9}, {%0,%1,%2,%3};"
                : "+f"(acc[t][0]), "+f"(acc[t][1]), "+f"(acc[t][2]), "+f"(acc[t][3])
                : "r"(a0), "r"(a1), "r"(a2), "r"(a3), "r"(b0), "r"(b2));
            asm volatile(
                "mma.sync.aligned.m16n8k16.row.col.f32.f16.f16.f32 "
                "{%0,%1,%2,%3}, {%4,%5,%6,%7}, {%8,%9}, {%0,%1,%2,%3};"
                : "+f"(acc[t+1][0]), "+f"(acc[t+1][1]), "+f"(acc[t+1][2]), "+f"(acc[t+1][3])
                : "r"(a0), "r"(a1), "r"(a2), "r"(a3), "r"(b1), "r"(b3));
        }
    }

    const int g_lo = row0 + w * 16 + r;
    const int g_hi = g_lo + 8;
    float p_lo = 0.f, p_hi = 0.f;
    #pragma unroll
    for (int t = 0; t < 16; t++) {
        int c = t * 8 + 2 * q;
        float av0 = __ldg(att + c), av1 = __ldg(att + c + 1);
        p_lo += acc[t][0] * av0 + acc[t][1] * av1;
        p_hi += acc[t][2] * av0 + acc[t][3] * av1;
        __half2 h01 = __floats2half2_rn(acc[t][0], acc[t][1]);
        __half2 h23 = __floats2half2_rn(acc[t][2], acc[t][3]);
        if (g_lo < n) *(__half2*)(Hout + (size_t)g_lo * HID + c) = h01;
        if (g_hi < n) *(__half2*)(Hout + (size_t)g_hi * HID + c) = h23;
    }
    p_lo += __shfl_xor_sync(0xFFFFFFFFu, p_lo, 1);
    p_lo += __shfl_xor_sync(0xFFFFFFFFu, p_lo, 2);
    p_hi += __shfl_xor_sync(0xFFFFFFFFu, p_hi, 1);
    p_hi += __shfl_xor_sync(0xFFFFFFFFu, p_hi, 2);
    if (q == 0) {
        if (g_lo < n) aout[g_lo] = p_lo;
        if (g_hi < n) aout[g_hi] = p_hi;
    }
}

// ---------------- single-pass scan with decoupled lookback ---------------------------
__global__ void __launch_bounds__(1024) scan_onepass_kernel(
    int* __restrict__ cursor, int* __restrict__ rowptr, int* __restrict__ aggs, int n)
{
    __shared__ int wsum[32];
    __shared__ int s_off;
    int et = blockIdx.y;
    int bid = blockIdx.x;
    const int* deg = cursor + (size_t)et * MAXN;
    int* rp = rowptr + (size_t)et * (MAXN + 1);
    int* cu = cursor + (size_t)et * MAXN;
    int* agg = aggs + (size_t)et * 64;
    int tid = threadIdx.x;
    int wid = tid >> 5, lane = tid & 31;
    int i = bid * 1024 + tid;
    int v = (i < n) ? deg[i] : 0;

    int x = v;
    #pragma unroll
    for (int off = 1; off < 32; off <<= 1) {
        int t = __shfl_up_sync(0xFFFFFFFFu, x, off);
        if (lane >= off) x += t;
    }
    if (lane == 31) wsum[wid] = x;
    __syncthreads();
    if (wid == 0) {
        int y = wsum[lane];
        #pragma unroll
        for (int off = 1; off < 32; off <<= 1) {
            int t = __shfl_up_sync(0xFFFFFFFFu, y, off);
            if (lane >= off) y += t;
        }
        wsum[lane] = y;
    }
    __syncthreads();
    int incl = x + (wid > 0 ? wsum[wid - 1] : 0);

    if (tid == 1023) atomicExch(agg + bid, incl);
    if (wid == 0) {
        int sum = 0;
        for (int j = lane; j < bid; j += 32) {
            int a;
            do { a = atomicAdd(agg + j, 0); } while (a < 0);
            sum += a;
        }
        #pragma unroll
        for (int o = 16; o; o >>= 1) sum += __shfl_xor_sync(0xFFFFFFFFu, sum, o);
        if (lane == 0) s_off = sum;
    }
    __syncthreads();
    int off = s_off;

    if (i < n) {
        int fin = incl + off;
        rp[i + 1] = fin;
        cu[i] = fin - v;
    }
    if (i == 0) rp[0] = 0;
}

// scatter: single atomic gives global position directly
__global__ void scatter2_kernel(const int* __restrict__ e0, const int* __restrict__ e1,
                                int* __restrict__ cursor, int* __restrict__ csrc, int ne)
{
    int et = blockIdx.y;
    const int* edges = et ? e1 : e0;
    int i = blockIdx.x * blockDim.x + threadIdx.x;
    if (i >= ne) return;
    int d = edges[ne + i];
    int pos = atomicAdd(cursor + (size_t)et * MAXN + d, 1);
    csrc[(size_t)et * MAXE + pos] = edges[i];
}

// ---------------- fused gather (both edge types via blockIdx.y) ----------------------
__global__ void __launch_bounds__(256) gather2_kernel(
    const int* __restrict__ rowptrB, const int* __restrict__ csrcB,
    const float* __restrict__ As0, const float* __restrict__ As1,
    const __half* __restrict__ Xp, const __half* __restrict__ Xa,
    const float* __restrict__ vbuf, int l,
    const __half* __restrict__ Hs0, const __half* __restrict__ Hs1,
    const float* __restrict__ biasB,
    __half* __restrict__ Out0, __half* __restrict__ Out1, int n)
{
    __shared__ float2 wsb[8][32];
    const int et = blockIdx.y;
    const int* rowptr = rowptrB + (size_t)et * (MAXN + 1);
    const int* csrc   = csrcB + (size_t)et * MAXE;
    const float* as_  = et ? As1 : As0;
    const __half* xdst = et ? Xp : Xa;
    const int pi = l * 2 + et;
    const float* v    = vbuf + pi * HID;
    const __half* hs  = et ? Hs1 : Hs0;
    const uint2* hrow = (const uint2*)hs;
    const float* bias = biasB + (size_t)pi * HID;
    __half* out = et ? Out1 : Out0;

    int node = (int)((blockIdx.x * (size_t)blockDim.x + threadIdx.x) >> 5);
    int wid  = (threadIdx.x >> 5);
    int lane = threadIdx.x & 31;
    if (node >= n) return;

    uint2 xu = __ldg((const uint2*)(xdst + (size_t)node * HID) + lane);
    float2 x01 = __half22float2(*(__half2*)&xu.x);
    float2 x23 = __half22float2(*(__half2*)&xu.y);
    float4 vv = __ldg((const float4*)v + lane);
    float add = x01.x*vv.x + x01.y*vv.y + x23.x*vv.z + x23.y*vv.w;
    #pragma unroll
    for (int o = 16; o; o >>= 1) add += __shfl_xor_sync(0xFFFFFFFFu, add, o);

    int b = __ldg(rowptr + node);
    int e = __ldg(rowptr + node + 1);

    float den = 0.f;
    float4 acc = make_float4(0.f, 0.f, 0.f, 0.f);
    for (int c = b; c < e; c += 32) {
        int i = c + lane;
        float ex = 0.f; int s = 0;
        if (i < e) {
            s = __ldg(csrc + i);
            float t = __ldg(as_ + s) + add;
            t = (t > 0.f) ? t : 0.2f * t;
            ex = expf(t);
        }
        den += ex;
        wsb[wid][lane] = make_float2(ex, __int_as_float(s));
        __syncwarp();
        int cnt = min(32, e - c);
        int j = 0;
        for (; j + 4 <= cnt; j += 4) {
            float2 p0 = wsb[wid][j],   p1 = wsb[wid][j+1];
            float2 p2 = wsb[wid][j+2], p3 = wsb[wid][j+3];
            uint2 u0 = __ldg(hrow + __float_as_int(p0.y) * 32 + lane);
            uint2 u1 = __ldg(hrow + __float_as_int(p1.y) * 32 + lane);
            uint2 u2 = __ldg(hrow + __float_as_int(p2.y) * 32 + lane);
            uint2 u3 = __ldg(hrow + __float_as_int(p3.y) * 32 + lane);
            float2 a01, a23;
            a01 = __half22float2(*(__half2*)&u0.x); a23 = __half22float2(*(__half2*)&u0.y);
            acc.x += p0.x * a01.x; acc.y += p0.x * a01.y;
            acc.z += p0.x * a23.x; acc.w += p0.x * a23.y;
            a01 = __half22float2(*(__half2*)&u1.x); a23 = __half22float2(*(__half2*)&u1.y);
            acc.x += p1.x * a01.x; acc.y += p1.x * a01.y;
            acc.z += p1.x * a23.x; acc.w += p1.x * a23.y;
            a01 = __half22float2(*(__half2*)&u2.x); a23 = __half22float2(*(__half2*)&u2.y);
            acc.x += p2.x * a01.x; acc.y += p2.x * a01.y;
            acc.z += p2.x * a23.x; acc.w += p2.x * a23.y;
            a01 = __half22float2(*(__half2*)&u3.x); a23 = __half22float2(*(__half2*)&u3.y);
            acc.x += p3.x * a01.x; acc.y += p3.x * a01.y;
            acc.z += p3.x * a23.x; acc.w += p3.x * a23.y;
        }
        for (; j < cnt; j++) {
            float2 p = wsb[wid][j];
            uint2 u = __ldg(hrow + __float_as_int(p.y) * 32 + lane);
            float2 f01 = __half22float2(*(__half2*)&u.x);
            float2 f23 = __half22float2(*(__half2*)&u.y);
            acc.x += p.x * f01.x; acc.y += p.x * f01.y;
            acc.z += p.x * f23.x; acc.w += p.x * f23.y;
        }
        __syncwarp();
    }
    #pragma unroll
    for (int o = 16; o; o >>= 1) den += __shfl_xor_sync(0xFFFFFFFFu, den, o);
    float inv = 1.f / (den + 1e-16f);

    float4 bb = __ldg((const float4*)bias + lane);
    __half2 o01 = __floats2half2_rn(fmaxf(acc.x * inv + bb.x, 0.f),
                                    fmaxf(acc.y * inv + bb.y, 0.f));
    __half2 o23 = __floats2half2_rn(fmaxf(acc.z * inv + bb.z, 0.f),
                                    fmaxf(acc.w * inv + bb.w, 0.f));
    ((uint2*)(out + (size_t)node * HID))[lane] =
        make_uint2(*(unsigned int*)&o01, *(unsigned int*)&o23);
}

// ---------------- pool both node types: 128-row slabs, atomicMax-as-int --------------
__global__ void pool2_kernel(const __half* __restrict__ Xp, const __half* __restrict__ Xa,
                             const int* __restrict__ bp, const int* __restrict__ ba,
                             float* __restrict__ pool, int n)
{
    int et = blockIdx.y;
    const __half* X = et ? Xa : Xp;
    const int* batch = et ? ba : bp;
    float* pl = pool + (size_t)et * 64 * HID;
    int row0 = blockIdx.x * 128;
    int row1 = min(row0 + 128, n);
    if (row0 >= n) return;
    int f = threadIdx.x;
    int curg = __ldg(batch + row0);
    float m = 0.f;
    for (int r = row0; r < row1; r++) {
        int g = __ldg(batch + r);
        if (g != curg) {
            atomicMax((int*)(pl + (size_t)curg * HID + f), __float_as_int(m));
            m = 0.f; curg = g;
        }
        m = fmaxf(m, __half2float(__ldg(X + (size_t)r * HID + f)));
    }
    atomicMax((int*)(pl + (size_t)curg * HID + f), __float_as_int(m));
}

// ---------------- final: out[t,g,o] = pool[t,g,:]@linW + linb ------------------------
__global__ void final_kernel(const float* __restrict__ pool, const float* __restrict__ linW,
                             const float* __restrict__ linb, float* __restrict__ out)
{
    int idx = blockIdx.x * blockDim.x + threadIdx.x;
    int o = idx & 15;
    int g = (idx >> 4) & 63;
    int t = idx >> 10;
    const float* pr = pool + (size_t)t * 64 * HID + (size_t)g * HID;
    float s = __ldg(linb + o);
    #pragma unroll 8
    for (int k = 0; k < HID; k++) s += pr[k] * __ldg(linW + k * 16 + o);
    out[idx] = s;
}

// ====================================================================================
extern "C" void kernel_launch(void* const* d_in, const int* in_sizes, int n_in,
                              void* d_out, int out_size)
{
    const float* x_paper     = (const float*)d_in[0];
    const float* x_author    = (const float*)d_in[1];
    const int*   edge_pa     = (const int*)d_in[2];
    const int*   edge_ap     = (const int*)d_in[3];
    const int*   batch_paper = (const int*)d_in[4];
    const int*   batch_author= (const int*)d_in[5];
    const float* Wsrc        = (const float*)d_in[6];
    const float* Wdst        = (const float*)d_in[7];
    const float* att_src     = (const float*)d_in[8];
    const float* att_dst     = (const float*)d_in[9];
    const float* bias        = (const float*)d_in[10];
    const float* linW        = (const float*)d_in[11];
    const float* linb        = (const float*)d_in[12];
    float* out = (float*)d_out;

    const int n  = in_sizes[0] / HID;
    const int ne = in_sizes[2] / 2;

    void* base = nullptr;
    cudaGetSymbolAddress(&base, g_scratch);
    float* S     = (float*)base;
    __half* hs0  = (__half*)(S + O_HS0);
    __half* hs1  = (__half*)(S + O_HS1);
    __half* xph  = (__half*)(S + O_XPH);
    __half* xah  = (__half*)(S + O_XAH);
    __half* nbuf[4] = { (__half*)(S + O_NB),
                        (__half*)(S + O_NB + NHs / 2),
                        (__half*)(S + O_NB + 2 * (NHs / 2)),
                        (__half*)(S + O_NB + 3 * (NHs / 2)) };
    float* as0  = S + O_AS0;
    float* as1  = S + O_AS1;
    float* vbuf = S + O_V;
    float* pool = S + O_POOL;
    __half* Wth = (__half*)(S + O_WT);

    void* rp_base = nullptr;  cudaGetSymbolAddress(&rp_base, g_rowptr);
    void* cs_base = nullptr;  cudaGetSymbolAddress(&cs_base, g_csrc);
    void* cu_base = nullptr;  cudaGetSymbolAddress(&cu_base, g_cursor);
    void* ag_base = nullptr;  cudaGetSymbolAddress(&ag_base, g_aggs);
    int* rowptr = (int*)rp_base;
    int* csrc   = (int*)cs_base;
    int* cursor = (int*)cu_base;
    int* aggs   = (int*)ag_base;

    const size_t smem = 2 * 128 * XS_STR * sizeof(__half);
    cudaFuncSetAttribute(gemm_mma2_kernel, cudaFuncAttributeMaxDynamicSharedMemorySize, (int)smem);

    const int gemm_blocks = (n + 127) / 128;
    const int edge_blocks = (ne + 255) / 256;
    const int hist_blocks = ((ne >> 2) + 255) / 256;
    const int warp_blocks = (n + 7) / 8;
    const int scan_blocks = (n + 1023) / 1024;
    const int pool_blocks = (n + 127) / 128;
    const int npool = 2 * 64 * HID;
    const int cvtb  = (2 * n * 32 + 255) / 256;
    const int zerob = (2 * MAXN + 255) / 256;
    const int wtb   = (4 * HID * HID + 255) / 256;

    // 1: convert X + zero cursors/pool + aggs sentinel + transpose-convert Wsrc
    prep_kernel<<<cvtb + zerob + wtb, 256>>>(x_paper, x_author, xph, cursor, pool, aggs,
                                             Wsrc, Wth, n * 32, cvtb, zerob, 2 * MAXN, npool);
    // 2: histogram (vectorized) + wv vectors
    {
        dim3 g(hist_blocks + 32, 2);
        hist_wv_kernel<<<g, 256>>>(edge_pa, edge_ap, cursor, ne, Wdst, att_dst, vbuf);
    }
    // 3: single-pass scan (decoupled lookback) -> rowptr + cursor row starts
    {
        dim3 g(scan_blocks, 2);
        scan_onepass_kernel<<<g, 1024>>>(cursor, rowptr, aggs, n);
    }
    // 4: layer-0 GEMMs
    {
        dim3 g(gemm_blocks, 2);
        gemm_mma2_kernel<<<g, 256, smem>>>(xph, xah, Wth, att_src, 0,
                                           hs0, hs1, as0, as1, n);
    }
    // 5: scatter (single atomic per edge)
    {
        dim3 g(edge_blocks, 2);
        scatter2_kernel<<<g, 256>>>(edge_pa, edge_ap, cursor, csrc, ne);
    }

    const __half* xp = xph;
    const __half* xa = xah;

    for (int l = 0; l < 2; l++) {
        if (l > 0) {
            dim3 g(gemm_blocks, 2);
            gemm_mma2_kernel<<<g, 256, smem>>>(xp, xa, Wth, att_src, l,
                                               hs0, hs1, as0, as1, n);
        }
        {
            dim3 g(warp_blocks, 2);
            gather2_kernel<<<g, 256>>>(rowptr, csrc, as0, as1, xp, xa, vbuf, l,
                                       hs0, hs1, bias, nbuf[l * 2 + 0], nbuf[l * 2 + 1], n);
        }
        xa = nbuf[l * 2 + 0];
        xp = nbuf[l * 2 + 1];
    }

    {
        dim3 g(pool_blocks, 2);
        pool2_kernel<<<g, HID>>>(xp, xa, batch_paper, batch_author, pool, n);
    }
    final_kernel<<<8, 256>>>(pool, linW, linb, out);
}

// round 17
// speedup vs baseline: 1.0454x; 1.0454x over previous
#include <cuda_runtime.h>
#include <cuda_bf16.h>
#include <cuda_fp16.h>
#include <math.h>

#define HID 128
#define MAXN 50000
#define MAXE 600000

// ---------------- scratch (static device memory; no allocs allowed) ----------------
static const size_t NHs   = (size_t)MAXN * HID;
static const size_t O_HS0  = 0;                       // __half[NHs]
static const size_t O_HS1  = O_HS0 + NHs / 2;         // __half[NHs]
static const size_t O_XPH  = O_HS1 + NHs / 2;         // __half[NHs]
static const size_t O_XAH  = O_XPH + NHs / 2;         // __half[NHs]
static const size_t O_NB   = O_XAH + NHs / 2;         // 4 x __half[NHs]
static const size_t O_AS0  = O_NB + 4 * (NHs / 2);
static const size_t O_AS1  = O_AS0 + MAXN + 64;
static const size_t O_V    = O_AS1 + MAXN + 64;       // 4 x 128 floats
static const size_t O_POOL = O_V + 4 * 128;
static const size_t O_WT   = O_POOL + 2 * 64 * HID;   // __half[4*128*128] transposed Wsrc
static const size_t SCRATCH_FLOATS = O_WT + 4 * HID * HID / 2;

__device__ float g_scratch[SCRATCH_FLOATS];
__device__ int   g_rowptr[2][MAXN + 1];
__device__ int   g_csrc[2][MAXE];
__device__ int   g_cursor[2][MAXN];
__device__ int   g_aggs[2][64];      // lookback aggregates (sentinel -1)

// ---------------- prep: f32->f16 convert inputs + zero cursors/pool + aggs + Wt ------
__global__ void prep_kernel(const float* __restrict__ Xp, const float* __restrict__ Xa,
                            __half* __restrict__ XhBase,
                            int* __restrict__ cursor, float* __restrict__ pool,
                            int* __restrict__ aggs,
                            const float* __restrict__ Wsrc, __half* __restrict__ Wth,
                            int per4, int cvtb, int zerob, int n2, int np)
{
    int bx = blockIdx.x;
    if (bx < cvtb) {
        int i = bx * 256 + threadIdx.x;
        if (i >= 2 * per4) return;
        const float* X = (i < per4) ? Xp : Xa;
        int j = (i < per4) ? i : i - per4;
        float4 v = __ldg((const float4*)X + j);
        __half2 h01 = __floats2half2_rn(v.x, v.y);
        __half2 h23 = __floats2half2_rn(v.z, v.w);
        ((uint2*)XhBase)[i] = make_uint2(*(unsigned int*)&h01, *(unsigned int*)&h23);
    } else if (bx < cvtb + zerob) {
        int i = (bx - cvtb) * 256 + threadIdx.x;
        if (i < n2) cursor[i] = 0;
        if (i < np) pool[i] = 0.f;
        if (i < 128) aggs[i] = -1;
    } else {
        int i = (bx - cvtb - zerob) * 256 + threadIdx.x;   // 0 .. 4*16384-1
        if (i >= 4 * HID * HID) return;
        int pi = i >> 14;
        int rem = i & 16383;
        int k = rem >> 7, nn = rem & 127;
        Wth[(size_t)pi * HID * HID + nn * HID + k] =
            __float2half(__ldg(Wsrc + (size_t)pi * HID * HID + k * HID + nn));
    }
}

// ---------------- hist (vectorized int4, both edge types) + wv vectors ---------------
__global__ void hist_wv_kernel(const int* __restrict__ e0, const int* __restrict__ e1,
                               int* __restrict__ cnt, int ne,
                               const float* __restrict__ Wdst,
                               const float* __restrict__ att_dst, float* __restrict__ vbuf)
{
    int et = blockIdx.y;
    int histb = gridDim.x - 32;
    if ((int)blockIdx.x < histb) {
        const int* dst = (et ? e1 : e0) + ne;
        int i4 = blockIdx.x * blockDim.x + threadIdx.x;
        int ne4 = ne >> 2;
        int* c = cnt + (size_t)et * MAXN;
        if (i4 < ne4) {
            int4 d = __ldg((const int4*)dst + i4);
            atomicAdd(c + d.x, 1);
            atomicAdd(c + d.y, 1);
            atomicAdd(c + d.z, 1);
            atomicAdd(c + d.w, 1);
        }
        int tail0 = ne4 << 2;
        int t = tail0 + i4;
        if (i4 < (ne - tail0)) atomicAdd(c + __ldg(dst + t), 1);
    } else {
        int dx = blockIdx.x - histb;
        int gw = (et * 32 + dx) * 8 + (threadIdx.x >> 5);
        int lane = threadIdx.x & 31;
        int pi = gw >> 7, k = gw & 127;
        float4 wv = __ldg((const float4*)(Wdst + (size_t)pi * HID * HID + (size_t)k * HID) + lane);
        float4 av = __ldg((const float4*)(att_dst + (size_t)pi * HID) + lane);
        float s = wv.x*av.x + wv.y*av.y + wv.z*av.z + wv.w*av.w;
        #pragma unroll
        for (int o = 16; o; o >>= 1) s += __shfl_xor_sync(0xFFFFFFFFu, s, o);
        if (lane == 0) vbuf[gw] = s;
    }
}

// ---------------- HMMA GEMM: ldmatrix mainloop + smem-staged coalesced epilogue ------
#define XS_STR 136
__global__ void __launch_bounds__(256) gemm_mma2_kernel(
    const __half* __restrict__ Xp, const __half* __restrict__ Xa,
    const __half* __restrict__ Wth, const float* __restrict__ att_src, int l,
    __half* __restrict__ Hs0, __half* __restrict__ Hs1,
    float* __restrict__ As0, float* __restrict__ As1, int n)
{
    const int et = blockIdx.y;
    const __half* X = et ? Xa : Xp;
    const int pi = l * 2 + et;
    const __half* Wt_g = Wth + (size_t)pi * HID * HID;
    const float* att = att_src + (size_t)pi * HID;
    __half* Hout = et ? Hs1 : Hs0;
    float*  aout = et ? As1 : As0;

    extern __shared__ __half sm[];
    __half* Xs = sm;
    __half* Wt = sm + 128 * XS_STR;

    const int tid  = threadIdx.x;
    const int row0 = blockIdx.x * 128;

    for (int i = tid; i < 128 * 16; i += 256) {
        int r = i >> 4, c8 = (i & 15) * 8;
        uint4 wv = __ldg((const uint4*)(Wt_g + r * HID + c8));
        *(uint4*)(Wt + r * XS_STR + c8) = wv;
        int gr = row0 + r;
        uint4 v = make_uint4(0u, 0u, 0u, 0u);
        if (gr < n) v = __ldg((const uint4*)(X + (size_t)gr * HID + c8));
        *(uint4*)(Xs + r * XS_STR + c8) = v;
    }
    __syncthreads();

    const int w    = tid >> 5;
    const int lane = tid & 31;
    const int r    = lane >> 2;
    const int q    = lane & 3;

    float acc[16][4];
    #pragma unroll
    for (int t = 0; t < 16; t++)
        #pragma unroll
        for (int j = 0; j < 4; j++) acc[t][j] = 0.f;

    unsigned int xs_addr = (unsigned int)__cvta_generic_to_shared(
        Xs + (w * 16 + (lane & 15)) * XS_STR + ((lane >> 4) << 3));
    unsigned int wt_addr = (unsigned int)__cvta_generic_to_shared(
        Wt + ((lane & 7) + ((lane >> 3) & 1) * 8) * XS_STR + ((lane >> 4) << 3));

    #pragma unroll
    for (int k0 = 0; k0 < HID; k0 += 16) {
        unsigned int a0, a1, a2, a3;
        asm volatile("ldmatrix.sync.aligned.m8n8.x4.shared.b16 {%0,%1,%2,%3}, [%4];"
                     : "=r"(a0), "=r"(a1), "=r"(a2), "=r"(a3)
                     : "r"(xs_addr + k0 * 2));
        #pragma unroll
        for (int t = 0; t < 16; t += 2) {
            unsigned int b0, b1, b2, b3;
            asm volatile("ldmatrix.sync.aligned.m8n8.x4.shared.b16 {%0,%1,%2,%3}, [%4];"
                         : "=r"(b0), "=r"(b1), "=r"(b2), "=r"(b3)
                         : "r"(wt_addr + (unsigned int)((t * 8 * XS_STR + k0) * 2)));
            asm volatile(
                "mma.sync.aligned.m16n8k16.row.col.f32.f16.f16.f32 "
                "{%0,%1,%2,%3}, {%4,%5,%6,%7}, {%8,%9}, {%0,%1,%2,%3};"
                : "+f"(acc[t][0]), "+f"(acc[t][1]), "+f"(acc[t][2]), "+f"(acc[t][3])
                : "r"(a0), "r"(a1), "r"(a2), "r"(a3), "r"(b0), "r"(b2));
            asm volatile(
                "mma.sync.aligned.m16n8k16.row.col.f32.f16.f16.f32 "
                "{%0,%1,%2,%3}, {%4,%5,%6,%7}, {%8,%9}, {%0,%1,%2,%3};"
                : "+f"(acc[t+1][0]), "+f"(acc[t+1][1]), "+f"(acc[t+1][2]), "+f"(acc[t+1][3])
                : "r"(a0), "r"(a1), "r"(a2), "r"(a3), "r"(b1), "r"(b3));
        }
    }

    // fused att dot from registers (cheap; scattered scalar writes OK for aout)
    const int g_lo = row0 + w * 16 + r;
    const int g_hi = g_lo + 8;
    float p_lo = 0.f, p_hi = 0.f;
    #pragma unroll
    for (int t = 0; t < 16; t++) {
        int c = t * 8 + 2 * q;
        float av0 = __ldg(att + c), av1 = __ldg(att + c + 1);
        p_lo += acc[t][0] * av0 + acc[t][1] * av1;
        p_hi += acc[t][2] * av0 + acc[t][3] * av1;
    }
    p_lo += __shfl_xor_sync(0xFFFFFFFFu, p_lo, 1);
    p_lo += __shfl_xor_sync(0xFFFFFFFFu, p_lo, 2);
    p_hi += __shfl_xor_sync(0xFFFFFFFFu, p_hi, 1);
    p_hi += __shfl_xor_sync(0xFFFFFFFFu, p_hi, 2);
    if (q == 0) {
        if (g_lo < n) aout[g_lo] = p_lo;
        if (g_hi < n) aout[g_hi] = p_hi;
    }

    // smem-staged coalesced store of H (reuse Xs tile)
    __syncthreads();
    __half* Cs = Xs;
    #pragma unroll
    for (int t = 0; t < 16; t++) {
        int c = t * 8 + 2 * q;
        *(__half2*)(Cs + (w * 16 + r) * XS_STR + c)     = __floats2half2_rn(acc[t][0], acc[t][1]);
        *(__half2*)(Cs + (w * 16 + r + 8) * XS_STR + c) = __floats2half2_rn(acc[t][2], acc[t][3]);
    }
    __syncthreads();
    for (int i = tid; i < 128 * 16; i += 256) {
        int rr = i >> 4, c8 = (i & 15) * 8;
        int gr = row0 + rr;
        if (gr < n)
            *(uint4*)(Hout + (size_t)gr * HID + c8) = *(const uint4*)(Cs + rr * XS_STR + c8);
    }
}

// ---------------- single-pass scan with decoupled lookback ---------------------------
__global__ void __launch_bounds__(1024) scan_onepass_kernel(
    int* __restrict__ cursor, int* __restrict__ rowptr, int* __restrict__ aggs, int n)
{
    __shared__ int wsum[32];
    __shared__ int s_off;
    int et = blockIdx.y;
    int bid = blockIdx.x;
    const int* deg = cursor + (size_t)et * MAXN;
    int* rp = rowptr + (size_t)et * (MAXN + 1);
    int* cu = cursor + (size_t)et * MAXN;
    int* agg = aggs + (size_t)et * 64;
    int tid = threadIdx.x;
    int wid = tid >> 5, lane = tid & 31;
    int i = bid * 1024 + tid;
    int v = (i < n) ? deg[i] : 0;

    int x = v;
    #pragma unroll
    for (int off = 1; off < 32; off <<= 1) {
        int t = __shfl_up_sync(0xFFFFFFFFu, x, off);
        if (lane >= off) x += t;
    }
    if (lane == 31) wsum[wid] = x;
    __syncthreads();
    if (wid == 0) {
        int y = wsum[lane];
        #pragma unroll
        for (int off = 1; off < 32; off <<= 1) {
            int t = __shfl_up_sync(0xFFFFFFFFu, y, off);
            if (lane >= off) y += t;
        }
        wsum[lane] = y;
    }
    __syncthreads();
    int incl = x + (wid > 0 ? wsum[wid - 1] : 0);

    if (tid == 1023) atomicExch(agg + bid, incl);
    if (wid == 0) {
        int sum = 0;
        for (int j = lane; j < bid; j += 32) {
            int a;
            do { a = atomicAdd(agg + j, 0); } while (a < 0);
            sum += a;
        }
        #pragma unroll
        for (int o = 16; o; o >>= 1) sum += __shfl_xor_sync(0xFFFFFFFFu, sum, o);
        if (lane == 0) s_off = sum;
    }
    __syncthreads();
    int off = s_off;

    if (i < n) {
        int fin = incl + off;
        rp[i + 1] = fin;
        cu[i] = fin - v;
    }
    if (i == 0) rp[0] = 0;
}

// scatter: single atomic gives global position directly
__global__ void scatter2_kernel(const int* __restrict__ e0, const int* __restrict__ e1,
                                int* __restrict__ cursor, int* __restrict__ csrc, int ne)
{
    int et = blockIdx.y;
    const int* edges = et ? e1 : e0;
    int i = blockIdx.x * blockDim.x + threadIdx.x;
    if (i >= ne) return;
    int d = edges[ne + i];
    int pos = atomicAdd(cursor + (size_t)et * MAXN + d, 1);
    csrc[(size_t)et * MAXE + pos] = edges[i];
}

// ---------------- fused gather (both edge types via blockIdx.y) ----------------------
__global__ void __launch_bounds__(256) gather2_kernel(
    const int* __restrict__ rowptrB, const int* __restrict__ csrcB,
    const float* __restrict__ As0, const float* __restrict__ As1,
    const __half* __restrict__ Xp, const __half* __restrict__ Xa,
    const float* __restrict__ vbuf, int l,
    const __half* __restrict__ Hs0, const __half* __restrict__ Hs1,
    const float* __restrict__ biasB,
    __half* __restrict__ Out0, __half* __restrict__ Out1, int n)
{
    __shared__ float2 wsb[8][32];
    const int et = blockIdx.y;
    const int* rowptr = rowptrB + (size_t)et * (MAXN + 1);
    const int* csrc   = csrcB + (size_t)et * MAXE;
    const float* as_  = et ? As1 : As0;
    const __half* xdst = et ? Xp : Xa;
    const int pi = l * 2 + et;
    const float* v    = vbuf + pi * HID;
    const __half* hs  = et ? Hs1 : Hs0;
    const uint2* hrow = (const uint2*)hs;
    const float* bias = biasB + (size_t)pi * HID;
    __half* out = et ? Out1 : Out0;

    int node = (int)((blockIdx.x * (size_t)blockDim.x + threadIdx.x) >> 5);
    int wid  = (threadIdx.x >> 5);
    int lane = threadIdx.x & 31;
    if (node >= n) return;

    uint2 xu = __ldg((const uint2*)(xdst + (size_t)node * HID) + lane);
    float2 x01 = __half22float2(*(__half2*)&xu.x);
    float2 x23 = __half22float2(*(__half2*)&xu.y);
    float4 vv = __ldg((const float4*)v + lane);
    float add = x01.x*vv.x + x01.y*vv.y + x23.x*vv.z + x23.y*vv.w;
    #pragma unroll
    for (int o = 16; o; o >>= 1) add += __shfl_xor_sync(0xFFFFFFFFu, add, o);

    int b = __ldg(rowptr + node);
    int e = __ldg(rowptr + node + 1);

    float den = 0.f;
    float4 acc = make_float4(0.f, 0.f, 0.f, 0.f);
    for (int c = b; c < e; c += 32) {
        int i = c + lane;
        float ex = 0.f; int s = 0;
        if (i < e) {
            s = __ldg(csrc + i);
            float t = __ldg(as_ + s) + add;
            t = (t > 0.f) ? t : 0.2f * t;
            ex = expf(t);
        }
        den += ex;
        wsb[wid][lane] = make_float2(ex, __int_as_float(s));
        __syncwarp();
        int cnt = min(32, e - c);
        int j = 0;
        for (; j + 4 <= cnt; j += 4) {
            float2 p0 = wsb[wid][j],   p1 = wsb[wid][j+1];
            float2 p2 = wsb[wid][j+2], p3 = wsb[wid][j+3];
            uint2 u0 = __ldg(hrow + __float_as_int(p0.y) * 32 + lane);
            uint2 u1 = __ldg(hrow + __float_as_int(p1.y) * 32 + lane);
            uint2 u2 = __ldg(hrow + __float_as_int(p2.y) * 32 + lane);
            uint2 u3 = __ldg(hrow + __float_as_int(p3.y) * 32 + lane);
            float2 a01, a23;
            a01 = __half22float2(*(__half2*)&u0.x); a23 = __half22float2(*(__half2*)&u0.y);
            acc.x += p0.x * a01.x; acc.y += p0.x * a01.y;
            acc.z += p0.x * a23.x; acc.w += p0.x * a23.y;
            a01 = __half22float2(*(__half2*)&u1.x); a23 = __half22float2(*(__half2*)&u1.y);
            acc.x += p1.x * a01.x; acc.y += p1.x * a01.y;
            acc.z += p1.x * a23.x; acc.w += p1.x * a23.y;
            a01 = __half22float2(*(__half2*)&u2.x); a23 = __half22float2(*(__half2*)&u2.y);
            acc.x += p2.x * a01.x; acc.y += p2.x * a01.y;
            acc.z += p2.x * a23.x; acc.w += p2.x * a23.y;
            a01 = __half22float2(*(__half2*)&u3.x); a23 = __half22float2(*(__half2*)&u3.y);
            acc.x += p3.x * a01.x; acc.y += p3.x * a01.y;
            acc.z += p3.x * a23.x; acc.w += p3.x * a23.y;
        }
        for (; j < cnt; j++) {
            float2 p = wsb[wid][j];
            uint2 u = __ldg(hrow + __float_as_int(p.y) * 32 + lane);
            float2 f01 = __half22float2(*(__half2*)&u.x);
            float2 f23 = __half22float2(*(__half2*)&u.y);
            acc.x += p.x * f01.x; acc.y += p.x * f01.y;
            acc.z += p.x * f23.x; acc.w += p.x * f23.y;
        }
        __syncwarp();
    }
    #pragma unroll
    for (int o = 16; o; o >>= 1) den += __shfl_xor_sync(0xFFFFFFFFu, den, o);
    float inv = 1.f / (den + 1e-16f);

    float4 bb = __ldg((const float4*)bias + lane);
    __half2 o01 = __floats2half2_rn(fmaxf(acc.x * inv + bb.x, 0.f),
                                    fmaxf(acc.y * inv + bb.y, 0.f));
    __half2 o23 = __floats2half2_rn(fmaxf(acc.z * inv + bb.z, 0.f),
                                    fmaxf(acc.w * inv + bb.w, 0.f));
    ((uint2*)(out + (size_t)node * HID))[lane] =
        make_uint2(*(unsigned int*)&o01, *(unsigned int*)&o23);
}

// ---------------- pool both node types: 128-row slabs, atomicMax-as-int --------------
__global__ void pool2_kernel(const __half* __restrict__ Xp, const __half* __restrict__ Xa,
                             const int* __restrict__ bp, const int* __restrict__ ba,
                             float* __restrict__ pool, int n)
{
    int et = blockIdx.y;
    const __half* X = et ? Xa : Xp;
    const int* batch = et ? ba : bp;
    float* pl = pool + (size_t)et * 64 * HID;
    int row0 = blockIdx.x * 128;
    int row1 = min(row0 + 128, n);
    if (row0 >= n) return;
    int f = threadIdx.x;
    int curg = __ldg(batch + row0);
    float m = 0.f;
    for (int r = row0; r < row1; r++) {
        int g = __ldg(batch + r);
        if (g != curg) {
            atomicMax((int*)(pl + (size_t)curg * HID + f), __float_as_int(m));
            m = 0.f; curg = g;
        }
        m = fmaxf(m, __half2float(__ldg(X + (size_t)r * HID + f)));
    }
    atomicMax((int*)(pl + (size_t)curg * HID + f), __float_as_int(m));
}

// ---------------- final: out[t,g,o] = pool[t,g,:]@linW + linb ------------------------
__global__ void final_kernel(const float* __restrict__ pool, const float* __restrict__ linW,
                             const float* __restrict__ linb, float* __restrict__ out)
{
    int idx = blockIdx.x * blockDim.x + threadIdx.x;
    int o = idx & 15;
    int g = (idx >> 4) & 63;
    int t = idx >> 10;
    const float* pr = pool + (size_t)t * 64 * HID + (size_t)g * HID;
    float s = __ldg(linb + o);
    #pragma unroll 8
    for (int k = 0; k < HID; k++) s += pr[k] * __ldg(linW + k * 16 + o);
    out[idx] = s;
}

// ====================================================================================
extern "C" void kernel_launch(void* const* d_in, const int* in_sizes, int n_in,
                              void* d_out, int out_size)
{
    const float* x_paper     = (const float*)d_in[0];
    const float* x_author    = (const float*)d_in[1];
    const int*   edge_pa     = (const int*)d_in[2];
    const int*   edge_ap     = (const int*)d_in[3];
    const int*   batch_paper = (const int*)d_in[4];
    const int*   batch_author= (const int*)d_in[5];
    const float* Wsrc        = (const float*)d_in[6];
    const float* Wdst        = (const float*)d_in[7];
    const float* att_src     = (const float*)d_in[8];
    const float* att_dst     = (const float*)d_in[9];
    const float* bias        = (const float*)d_in[10];
    const float* linW        = (const float*)d_in[11];
    const float* linb        = (const float*)d_in[12];
    float* out = (float*)d_out;

    const int n  = in_sizes[0] / HID;
    const int ne = in_sizes[2] / 2;

    void* base = nullptr;
    cudaGetSymbolAddress(&base, g_scratch);
    float* S     = (float*)base;
    __half* hs0  = (__half*)(S + O_HS0);
    __half* hs1  = (__half*)(S + O_HS1);
    __half* xph  = (__half*)(S + O_XPH);
    __half* xah  = (__half*)(S + O_XAH);
    __half* nbuf[4] = { (__half*)(S + O_NB),
                        (__half*)(S + O_NB + NHs / 2),
                        (__half*)(S + O_NB + 2 * (NHs / 2)),
                        (__half*)(S + O_NB + 3 * (NHs / 2)) };
    float* as0  = S + O_AS0;
    float* as1  = S + O_AS1;
    float* vbuf = S + O_V;
    float* pool = S + O_POOL;
    __half* Wth = (__half*)(S + O_WT);

    void* rp_base = nullptr;  cudaGetSymbolAddress(&rp_base, g_rowptr);
    void* cs_base = nullptr;  cudaGetSymbolAddress(&cs_base, g_csrc);
    void* cu_base = nullptr;  cudaGetSymbolAddress(&cu_base, g_cursor);
    void* ag_base = nullptr;  cudaGetSymbolAddress(&ag_base, g_aggs);
    int* rowptr = (int*)rp_base;
    int* csrc   = (int*)cs_base;
    int* cursor = (int*)cu_base;
    int* aggs   = (int*)ag_base;

    const size_t smem = 2 * 128 * XS_STR * sizeof(__half);
    cudaFuncSetAttribute(gemm_mma2_kernel, cudaFuncAttributeMaxDynamicSharedMemorySize, (int)smem);

    const int gemm_blocks = (n + 127) / 128;
    const int edge_blocks = (ne + 255) / 256;
    const int hist_blocks = ((ne >> 2) + 255) / 256;
    const int warp_blocks = (n + 7) / 8;
    const int scan_blocks = (n + 1023) / 1024;
    const int pool_blocks = (n + 127) / 128;
    const int npool = 2 * 64 * HID;
    const int cvtb  = (2 * n * 32 + 255) / 256;
    const int zerob = (2 * MAXN + 255) / 256;
    const int wtb   = (4 * HID * HID + 255) / 256;

    // 1: convert X + zero cursors/pool + aggs sentinel + transpose-convert Wsrc
    prep_kernel<<<cvtb + zerob + wtb, 256>>>(x_paper, x_author, xph, cursor, pool, aggs,
                                             Wsrc, Wth, n * 32, cvtb, zerob, 2 * MAXN, npool);
    // 2: histogram (vectorized) + wv vectors
    {
        dim3 g(hist_blocks + 32, 2);
        hist_wv_kernel<<<g, 256>>>(edge_pa, edge_ap, cursor, ne, Wdst, att_dst, vbuf);
    }
    // 3: single-pass scan (decoupled lookback) -> rowptr + cursor row starts
    {
        dim3 g(scan_blocks, 2);
        scan_onepass_kernel<<<g, 1024>>>(cursor, rowptr, aggs, n);
    }
    // 4: layer-0 GEMMs
    {
        dim3 g(gemm_blocks, 2);
        gemm_mma2_kernel<<<g, 256, smem>>>(xph, xah, Wth, att_src, 0,
                                           hs0, hs1, as0, as1, n);
    }
    // 5: scatter (single atomic per edge)
    {
        dim3 g(edge_blocks, 2);
        scatter2_kernel<<<g, 256>>>(edge_pa, edge_ap, cursor, csrc, ne);
    }

    const __half* xp = xph;
    const __half* xa = xah;

    for (int l = 0; l < 2; l++) {
        if (l > 0) {
            dim3 g(gemm_blocks, 2);
            gemm_mma2_kernel<<<g, 256, smem>>>(xp, xa, Wth, att_src, l,
                                               hs0, hs1, as0, as1, n);
        }
        {
            dim3 g(warp_blocks, 2);
            gather2_kernel<<<g, 256>>>(rowptr, csrc, as0, as1, xp, xa, vbuf, l,
                                       hs0, hs1, bias, nbuf[l * 2 + 0], nbuf[l * 2 + 1], n);
        }
        xa = nbuf[l * 2 + 0];
        xp = nbuf[l * 2 + 1];
    }

    {
        dim3 g(pool_blocks, 2);
        pool2_kernel<<<g, HID>>>(xp, xa, batch_paper, batch_author, pool, n);
    }
    final_kernel<<<8, 256>>>(pool, linW, linb, out);
}